// round 1
// baseline (speedup 1.0000x reference)
#include <cuda_runtime.h>
#include <cstdint>

// ---------------------------------------------------------------------------
// LocallyConnectedNetwork: 7 unshared-weight conv stages + linear head + softmax.
// Strategy: keep activations in [C, H, W, B] (batch innermost) so all patch
// gathers are coalesced along B. Each stage = per-output-position mini-GEMM
//   out[Cout, B_tile] = W[i,j][Cout, K] * patch[K, B_tile]
// done as a smem-tiled fp32 GEMM with KC=32 K-chunks.
// ---------------------------------------------------------------------------

#define BMAX 32768

// Scratch (allocation-free rule: __device__ globals)
__device__ float g_xT[5 * 20 * 20 * (size_t)BMAX];        // 256 MB  transposed input
__device__ float g_bufA[4096ull * BMAX];                  // 512 MB  stages 1,3,5,7 out
__device__ float g_bufB[2304ull * BMAX];                  // 288 MB  stages 2,4,6 out

// ---------------------------------------------------------------------------
// 2D transpose: in[R, C] -> out[C, R]   (R = B, C = features)
// ---------------------------------------------------------------------------
__global__ void transpose2d(const float* __restrict__ in, float* __restrict__ out,
                            int R, int C) {
    __shared__ float t[32][33];
    int c = blockIdx.x * 32 + threadIdx.x;
    int r = blockIdx.y * 32 + threadIdx.y;
#pragma unroll
    for (int k = 0; k < 32; k += 8) {
        if (c < C) t[threadIdx.y + k][threadIdx.x] = in[(size_t)(r + k) * C + c];
    }
    __syncthreads();
    int co = blockIdx.y * 32 + threadIdx.x;   // output column = original row (B)
    int ro = blockIdx.x * 32 + threadIdx.y;   // output row    = original col (feature)
#pragma unroll
    for (int k = 0; k < 32; k += 8) {
        if (ro + k < C) out[(size_t)(ro + k) * R + co] = t[threadIdx.x][threadIdx.y + k];
    }
}

// ---------------------------------------------------------------------------
// One locally-connected stage.
//  xin : [CI, HI, WI, B]
//  W   : [HO, WO, CO, CI*KK*KK]
//  bias: [HO, WO, CO]
//  out : [CO, HO, WO, B]
// Block: one output position (i,j) x TB batch samples. 256 threads.
// Thread tile: TM(=4) samples x TN channels.
// ---------------------------------------------------------------------------
template <int HO, int WO, int CO, int CI, int KK, int HI, int WI,
          int TB, int TM, int TN, int KC>
__global__ void __launch_bounds__(256)
lc_stage(const float* __restrict__ xin, const float* __restrict__ W,
         const float* __restrict__ bias, float* __restrict__ out, int B) {
    constexpr int KTOT = CI * KK * KK;
    constexpr int BT = TB / TM;       // threads along batch
    constexpr int CT = CO / TN;       // threads along channels
    static_assert(BT * CT == 256, "thread shape");
    static_assert(TM == 4, "float4 batch tile");

    __shared__ float Ws[KC][CO];
    __shared__ float Ps[KC][TB];

    const int pos = blockIdx.x;
    const int i = pos / WO;
    const int j = pos % WO;
    const int b0 = blockIdx.y * TB;

    const int tid = threadIdx.x;
    const int tb = tid % BT;          // batch group
    const int tc = tid / BT;          // channel group

    const float* Wp = W + (size_t)pos * CO * KTOT;

    float acc[TM][TN];
#pragma unroll
    for (int m = 0; m < TM; ++m)
#pragma unroll
        for (int n = 0; n < TN; ++n) acc[m][n] = 0.f;

    for (int kc = 0; kc < KTOT; kc += KC) {
        // --- load weight chunk: Ws[kl][co] = W[pos, co, kc+kl] ---
        for (int idx = tid; idx < KC * CO; idx += 256) {
            int co = idx / KC;
            int kl = idx % KC;
            int kk = kc + kl;
            Ws[kl][co] = (kk < KTOT) ? Wp[(size_t)co * KTOT + kk] : 0.f;
        }
        // --- load patch chunk: Ps[kl][bq] = x[c, i+r, j+s, b0+bq] (coalesced in B) ---
        for (int idx = tid; idx < KC * (TB / 4); idx += 256) {
            int kl = idx / (TB / 4);
            int bq = idx % (TB / 4);
            int kk = kc + kl;
            float4 v = make_float4(0.f, 0.f, 0.f, 0.f);
            if (kk < KTOT) {
                int c   = kk / (KK * KK);
                int rem = kk - c * KK * KK;
                int r   = rem / KK;
                int s   = rem - r * KK;
                const float* src =
                    xin + (size_t)((c * HI + (i + r)) * WI + (j + s)) * B + b0 + bq * 4;
                v = *(const float4*)src;
            }
            *(float4*)&Ps[kl][bq * 4] = v;
        }
        __syncthreads();

        // --- compute ---
#pragma unroll
        for (int kl = 0; kl < KC; ++kl) {
            float4 pv = *(const float4*)&Ps[kl][tb * TM];
            float wv[TN];
#pragma unroll
            for (int n = 0; n < TN; ++n) wv[n] = Ws[kl][tc * TN + n];
#pragma unroll
            for (int n = 0; n < TN; ++n) {
                acc[0][n] += pv.x * wv[n];
                acc[1][n] += pv.y * wv[n];
                acc[2][n] += pv.z * wv[n];
                acc[3][n] += pv.w * wv[n];
            }
        }
        __syncthreads();
    }

    // --- epilogue: bias + tanh, vectorized store along B ---
#pragma unroll
    for (int n = 0; n < TN; ++n) {
        int co = tc * TN + n;
        float bv = bias[(size_t)pos * CO + co];
        float4 o;
        o.x = tanhf(acc[0][n] + bv);
        o.y = tanhf(acc[1][n] + bv);
        o.z = tanhf(acc[2][n] + bv);
        o.w = tanhf(acc[3][n] + bv);
        float* dst = out + (size_t)((co * HO + i) * WO + j) * B + b0 + tb * TM;
        *(float4*)dst = o;
    }
}

// ---------------------------------------------------------------------------
// Head: h[256, B] (stage7 out, NCHW-flatten order) ++ info[B,8] -> softmax(2)
// ---------------------------------------------------------------------------
__global__ void head_kernel(const float* __restrict__ h, const float* __restrict__ info,
                            const float* __restrict__ hw, const float* __restrict__ hb,
                            float* __restrict__ out, int B) {
    __shared__ float w0[264], w1[264];
    for (int idx = threadIdx.x; idx < 264; idx += blockDim.x) {
        w0[idx] = hw[idx];
        w1[idx] = hw[264 + idx];
    }
    __syncthreads();
    int b = blockIdx.x * blockDim.x + threadIdx.x;
    if (b >= B) return;
    float l0 = hb[0], l1 = hb[1];
#pragma unroll 8
    for (int f = 0; f < 256; ++f) {
        float v = h[(size_t)f * B + b];
        l0 += v * w0[f];
        l1 += v * w1[f];
    }
#pragma unroll
    for (int q = 0; q < 8; ++q) {
        float v = info[(size_t)b * 8 + q];
        l0 += v * w0[256 + q];
        l1 += v * w1[256 + q];
    }
    float m = fmaxf(l0, l1);
    float e0 = expf(l0 - m), e1 = expf(l1 - m);
    float inv = 1.f / (e0 + e1);
    out[(size_t)b * 2 + 0] = e0 * inv;
    out[(size_t)b * 2 + 1] = e1 * inv;
}

// ---------------------------------------------------------------------------
// launch
// ---------------------------------------------------------------------------
extern "C" void kernel_launch(void* const* d_in, const int* in_sizes, int n_in,
                              void* d_out, int out_size) {
    const float* x      = (const float*)d_in[0];
    const float* info   = (const float*)d_in[1];
    const float* W1 = (const float*)d_in[2];  const float* b1 = (const float*)d_in[3];
    const float* W2 = (const float*)d_in[4];  const float* b2 = (const float*)d_in[5];
    const float* W3 = (const float*)d_in[6];  const float* b3 = (const float*)d_in[7];
    const float* W4 = (const float*)d_in[8];  const float* b4 = (const float*)d_in[9];
    const float* W5 = (const float*)d_in[10]; const float* b5 = (const float*)d_in[11];
    const float* W6 = (const float*)d_in[12]; const float* b6 = (const float*)d_in[13];
    const float* W7 = (const float*)d_in[14]; const float* b7 = (const float*)d_in[15];
    const float* hw = (const float*)d_in[16]; const float* hb = (const float*)d_in[17];
    float* out = (float*)d_out;

    const int B = in_sizes[0] / (5 * 20 * 20);

    float *xT, *bufA, *bufB;
    cudaGetSymbolAddress((void**)&xT,   g_xT);
    cudaGetSymbolAddress((void**)&bufA, g_bufA);
    cudaGetSymbolAddress((void**)&bufB, g_bufB);

    // transpose input [B, 2000] -> [2000, B]
    {
        dim3 grid((2000 + 31) / 32, B / 32), block(32, 8);
        transpose2d<<<grid, block>>>(x, xT, B, 2000);
    }

    // stage 1: 20x20x5 -> 16x16x16, k=5   (K=125)
    lc_stage<16,16,16, 5,5, 20,20, 128,4,2,32>
        <<<dim3(16*16, B/128), 256>>>(xT, W1, b1, bufA, B);
    // stage 2: 16x16x16 -> 12x12x16, k=5  (K=400)
    lc_stage<12,12,16, 16,5, 16,16, 128,4,2,32>
        <<<dim3(12*12, B/128), 256>>>(bufA, W2, b2, bufB, B);
    // stage 3: 12x12x16 -> 10x10x32, k=3  (K=144)
    lc_stage<10,10,32, 16,3, 12,12, 128,4,4,32>
        <<<dim3(10*10, B/128), 256>>>(bufB, W3, b3, bufA, B);
    // stage 4: 10x10x32 -> 8x8x32, k=3    (K=288)
    lc_stage<8,8,32, 32,3, 10,10, 128,4,4,32>
        <<<dim3(8*8, B/128), 256>>>(bufA, W4, b4, bufB, B);
    // stage 5: 8x8x32 -> 6x6x32, k=3      (K=288)
    lc_stage<6,6,32, 32,3, 8,8, 128,4,4,32>
        <<<dim3(6*6, B/128), 256>>>(bufB, W5, b5, bufA, B);
    // stage 6: 6x6x32 -> 4x4x64, k=3      (K=288)
    lc_stage<4,4,64, 32,3, 6,6, 64,4,4,32>
        <<<dim3(4*4, B/64), 256>>>(bufA, W6, b6, bufB, B);
    // stage 7: 4x4x64 -> 2x2x64, k=3      (K=576)
    lc_stage<2,2,64, 64,3, 4,4, 64,4,4,32>
        <<<dim3(2*2, B/64), 256>>>(bufB, W7, b7, bufA, B);

    // head: bufA is [64,2,2,B] == [256, B] in NCHW-flatten order
    head_kernel<<<(B + 255) / 256, 256>>>(bufA, info, hw, hb, out, B);
}

// round 2
// speedup vs baseline: 1.3213x; 1.3213x over previous
#include <cuda_runtime.h>
#include <cstdint>

// ---------------------------------------------------------------------------
// LocallyConnectedNetwork: 7 unshared-weight conv stages + linear head + softmax.
// Activations kept in [C, H, W, B] (batch innermost) -> coalesced patch loads.
// Each stage = per-output-position mini-GEMM with TM=8 x TN=8 register tiles.
// ---------------------------------------------------------------------------

#define BMAX 32768

__device__ float g_xT[5 * 20 * 20 * (size_t)BMAX];        // transposed input
__device__ float g_bufA[4096ull * BMAX];                  // stages 1,3,5,7 out
__device__ float g_bufB[2304ull * BMAX];                  // stages 2,4,6 out

// ---------------------------------------------------------------------------
__global__ void transpose2d(const float* __restrict__ in, float* __restrict__ out,
                            int R, int C) {
    __shared__ float t[32][33];
    int c = blockIdx.x * 32 + threadIdx.x;
    int r = blockIdx.y * 32 + threadIdx.y;
#pragma unroll
    for (int k = 0; k < 32; k += 8) {
        if (c < C) t[threadIdx.y + k][threadIdx.x] = in[(size_t)(r + k) * C + c];
    }
    __syncthreads();
    int co = blockIdx.y * 32 + threadIdx.x;
    int ro = blockIdx.x * 32 + threadIdx.y;
#pragma unroll
    for (int k = 0; k < 32; k += 8) {
        if (ro + k < C) out[(size_t)(ro + k) * R + co] = t[threadIdx.x][threadIdx.y + k];
    }
}

// ---------------------------------------------------------------------------
//  xin : [CI, HI, WI, B]
//  W   : [HO, WO, CO, CI*KK*KK]
//  bias: [HO, WO, CO]
//  out : [CO, HO, WO, B]
// Block: one output position x TB batch samples, 256 threads.
// Thread tile: TM=8 samples x TN=8 channels (64 FMA per k-step).
// Weight smem loads are warp-uniform (broadcast): tc = tid / BT, BT >= 32.
// ---------------------------------------------------------------------------
template <int HO, int WO, int CO, int CI, int KK, int HI, int WI, int KC>
__global__ void __launch_bounds__(256)
lc_stage(const float* __restrict__ xin, const float* __restrict__ W,
         const float* __restrict__ bias, float* __restrict__ out, int B) {
    constexpr int KTOT = CI * KK * KK;
    constexpr int TN = 8;
    constexpr int TM = 8;
    constexpr int CT = CO / TN;           // thread groups over channels
    constexpr int BT = 256 / CT;          // threads along batch
    constexpr int TB = BT * TM;           // batch tile
    static_assert(BT >= 32, "warp-uniform tc requires BT >= 32");
    static_assert(KC * TB * 4 <= 32768, "patch smem");

    __shared__ float Ws[KC][CO];
    __shared__ float Ps[KC][TB];

    const int pos = blockIdx.x;
    const int i = pos / WO;
    const int j = pos % WO;
    const int b0 = blockIdx.y * TB;

    const int tid = threadIdx.x;
    const int tb = tid % BT;
    const int tc = tid / BT;              // warp-uniform

    const float* Wp = W + (size_t)pos * CO * KTOT;

    float acc[TM][TN];
#pragma unroll
    for (int m = 0; m < TM; ++m)
#pragma unroll
        for (int n = 0; n < TN; ++n) acc[m][n] = 0.f;

    for (int kc = 0; kc < KTOT; kc += KC) {
        // weights: Ws[kl][co] = W[pos, co, kc+kl]
        for (int idx = tid; idx < KC * CO; idx += 256) {
            int co = idx / KC;
            int kl = idx % KC;
            int kk = kc + kl;
            Ws[kl][co] = (kk < KTOT) ? Wp[(size_t)co * KTOT + kk] : 0.f;
        }
        // patches: Ps[kl][b] = x[c, i+r, j+s, b0+b]  (coalesced along B)
        for (int idx = tid; idx < KC * (TB / 4); idx += 256) {
            int kl = idx / (TB / 4);
            int bq = idx % (TB / 4);
            int kk = kc + kl;
            float4 v = make_float4(0.f, 0.f, 0.f, 0.f);
            if (kk < KTOT) {
                int c   = kk / (KK * KK);
                int rem = kk - c * KK * KK;
                int r   = rem / KK;
                int s   = rem - r * KK;
                const float* src =
                    xin + (size_t)((c * HI + (i + r)) * WI + (j + s)) * B + b0 + bq * 4;
                v = *(const float4*)src;
            }
            *(float4*)&Ps[kl][bq * 4] = v;
        }
        __syncthreads();

#pragma unroll 8
        for (int kl = 0; kl < KC; ++kl) {
            float4 p0 = *(const float4*)&Ps[kl][tb * TM];
            float4 p1 = *(const float4*)&Ps[kl][tb * TM + 4];
            float4 w0 = *(const float4*)&Ws[kl][tc * TN];
            float4 w1 = *(const float4*)&Ws[kl][tc * TN + 4];
            float p[TM] = {p0.x, p0.y, p0.z, p0.w, p1.x, p1.y, p1.z, p1.w};
            float w[TN] = {w0.x, w0.y, w0.z, w0.w, w1.x, w1.y, w1.z, w1.w};
#pragma unroll
            for (int m = 0; m < TM; ++m)
#pragma unroll
                for (int n = 0; n < TN; ++n) acc[m][n] += p[m] * w[n];
        }
        __syncthreads();
    }

    // epilogue: bias + tanh, vectorized along B
#pragma unroll
    for (int n = 0; n < TN; ++n) {
        int co = tc * TN + n;
        float bv = bias[(size_t)pos * CO + co];
        float* dst = out + (size_t)((co * HO + i) * WO + j) * B + b0 + tb * TM;
        float4 o0, o1;
        o0.x = tanhf(acc[0][n] + bv);
        o0.y = tanhf(acc[1][n] + bv);
        o0.z = tanhf(acc[2][n] + bv);
        o0.w = tanhf(acc[3][n] + bv);
        o1.x = tanhf(acc[4][n] + bv);
        o1.y = tanhf(acc[5][n] + bv);
        o1.z = tanhf(acc[6][n] + bv);
        o1.w = tanhf(acc[7][n] + bv);
        *(float4*)dst = o0;
        *(float4*)(dst + 4) = o1;
    }
}

// ---------------------------------------------------------------------------
__global__ void head_kernel(const float* __restrict__ h, const float* __restrict__ info,
                            const float* __restrict__ hw, const float* __restrict__ hb,
                            float* __restrict__ out, int B) {
    __shared__ float w0[264], w1[264];
    for (int idx = threadIdx.x; idx < 264; idx += blockDim.x) {
        w0[idx] = hw[idx];
        w1[idx] = hw[264 + idx];
    }
    __syncthreads();
    int b = blockIdx.x * blockDim.x + threadIdx.x;
    if (b >= B) return;
    float l0 = hb[0], l1 = hb[1];
#pragma unroll 8
    for (int f = 0; f < 256; ++f) {
        float v = h[(size_t)f * B + b];
        l0 += v * w0[f];
        l1 += v * w1[f];
    }
#pragma unroll
    for (int q = 0; q < 8; ++q) {
        float v = info[(size_t)b * 8 + q];
        l0 += v * w0[256 + q];
        l1 += v * w1[256 + q];
    }
    float m = fmaxf(l0, l1);
    float e0 = expf(l0 - m), e1 = expf(l1 - m);
    float inv = 1.f / (e0 + e1);
    out[(size_t)b * 2 + 0] = e0 * inv;
    out[(size_t)b * 2 + 1] = e1 * inv;
}

// ---------------------------------------------------------------------------
extern "C" void kernel_launch(void* const* d_in, const int* in_sizes, int n_in,
                              void* d_out, int out_size) {
    const float* x      = (const float*)d_in[0];
    const float* info   = (const float*)d_in[1];
    const float* W1 = (const float*)d_in[2];  const float* b1 = (const float*)d_in[3];
    const float* W2 = (const float*)d_in[4];  const float* b2 = (const float*)d_in[5];
    const float* W3 = (const float*)d_in[6];  const float* b3 = (const float*)d_in[7];
    const float* W4 = (const float*)d_in[8];  const float* b4 = (const float*)d_in[9];
    const float* W5 = (const float*)d_in[10]; const float* b5 = (const float*)d_in[11];
    const float* W6 = (const float*)d_in[12]; const float* b6 = (const float*)d_in[13];
    const float* W7 = (const float*)d_in[14]; const float* b7 = (const float*)d_in[15];
    const float* hw = (const float*)d_in[16]; const float* hb = (const float*)d_in[17];
    float* out = (float*)d_out;

    const int B = in_sizes[0] / (5 * 20 * 20);

    float *xT, *bufA, *bufB;
    cudaGetSymbolAddress((void**)&xT,   g_xT);
    cudaGetSymbolAddress((void**)&bufA, g_bufA);
    cudaGetSymbolAddress((void**)&bufB, g_bufB);

    {
        dim3 grid((2000 + 31) / 32, B / 32), block(32, 8);
        transpose2d<<<grid, block>>>(x, xT, B, 2000);
    }

    // stage 1: 20x20x5 -> 16x16x16, k=5   (K=125)  TB=1024
    lc_stage<16,16,16, 5,5, 20,20, 8>
        <<<dim3(16*16, B/1024), 256>>>(xT, W1, b1, bufA, B);
    // stage 2: 16x16x16 -> 12x12x16, k=5  (K=400)  TB=1024
    lc_stage<12,12,16, 16,5, 16,16, 8>
        <<<dim3(12*12, B/1024), 256>>>(bufA, W2, b2, bufB, B);
    // stage 3: 12x12x16 -> 10x10x32, k=3  (K=144)  TB=512
    lc_stage<10,10,32, 16,3, 12,12, 16>
        <<<dim3(10*10, B/512), 256>>>(bufB, W3, b3, bufA, B);
    // stage 4: 10x10x32 -> 8x8x32, k=3    (K=288)  TB=512
    lc_stage<8,8,32, 32,3, 10,10, 16>
        <<<dim3(8*8, B/512), 256>>>(bufA, W4, b4, bufB, B);
    // stage 5: 8x8x32 -> 6x6x32, k=3      (K=288)  TB=512
    lc_stage<6,6,32, 32,3, 8,8, 16>
        <<<dim3(6*6, B/512), 256>>>(bufB, W5, b5, bufA, B);
    // stage 6: 6x6x32 -> 4x4x64, k=3      (K=288)  TB=256
    lc_stage<4,4,64, 32,3, 6,6, 32>
        <<<dim3(4*4, B/256), 256>>>(bufA, W6, b6, bufB, B);
    // stage 7: 4x4x64 -> 2x2x64, k=3      (K=576)  TB=256
    lc_stage<2,2,64, 64,3, 4,4, 32>
        <<<dim3(2*2, B/256), 256>>>(bufB, W7, b7, bufA, B);

    // head: bufA holds [64,2,2,B] == [256, B] in NCHW-flatten order
    head_kernel<<<(B + 255) / 256, 256>>>(bufA, info, hw, hb, out, B);
}

// round 8
// speedup vs baseline: 1.3450x; 1.0179x over previous
#include <cuda_runtime.h>
#include <cuda_bf16.h>
#include <cstdint>

#define BMAX 32768

__device__ float g_xT[5 * 20 * 20 * (size_t)BMAX];
__device__ float g_bufA[4096ull * BMAX];
__device__ float g_bufB[2304ull * BMAX];
__device__ unsigned char g_wt[15 * 1024 * 1024];   // pre-split bf16 hi/lo weight chunks

// ---------------------------------------------------------------------------
__global__ void transpose2d(const float* __restrict__ in, float* __restrict__ out,
                            int R, int C) {
    __shared__ float t[32][33];
    int c = blockIdx.x * 32 + threadIdx.x;
    int r = blockIdx.y * 32 + threadIdx.y;
#pragma unroll
    for (int k = 0; k < 32; k += 8)
        if (c < C) t[threadIdx.y + k][threadIdx.x] = in[(size_t)(r + k) * C + c];
    __syncthreads();
    int co = blockIdx.y * 32 + threadIdx.x;
    int ro = blockIdx.x * 32 + threadIdx.y;
#pragma unroll
    for (int k = 0; k < 32; k += 8)
        if (ro + k < C) out[(size_t)(ro + k) * R + co] = t[threadIdx.x][threadIdx.y + k];
}

// ---------------------------------------------------------------------------
// Weight prep: W[pos][CO][K] fp32 -> bf16 hi tile + lo tile.
// Layout per position: hi tile = NCH chunks; chunk c holds rows n of 17
// uint32 words (34 bf16, last word pad) covering k = c*32 .. c*32+31 as
// 16 bf16-pairs. lo tile follows at +TILE. Rows padded to 68B so the
// in-kernel copy is a straight uint4 memcpy into padded smem rows.
// ---------------------------------------------------------------------------
template <int CO, int K>
__global__ void prep_w(const float* __restrict__ W, unsigned char* __restrict__ wt) {
    constexpr int KPAD = ((K + 31) / 32) * 32;
    constexpr int NCH = KPAD / 32;
    constexpr int CHB = CO * 68;
    constexpr int TILE = NCH * CHB;
    const int pos = blockIdx.x;
    unsigned char* dst = wt + (size_t)pos * 2 * TILE;
    const float* src = W + (size_t)pos * CO * K;
    for (int idx = threadIdx.x; idx < CO * KPAD; idx += blockDim.x) {
        int n = idx / KPAD, k = idx % KPAD;
        float v = (k < K) ? src[n * K + k] : 0.f;
        __nv_bfloat16 h = __float2bfloat16(v);
        __nv_bfloat16 l = __float2bfloat16(v - __bfloat162float(h));
        uint32_t byte = (uint32_t)(k >> 5) * CHB + (uint32_t)n * 68 + (uint32_t)(k & 31) * 2;
        *(__nv_bfloat16*)(dst + byte) = h;
        *(__nv_bfloat16*)(dst + TILE + byte) = l;
    }
}

// ---------------------------------------------------------------------------
#define MMA_BF16(d, a, b0_, b1_) \
    asm volatile("mma.sync.aligned.m16n8k16.row.col.f32.bf16.bf16.f32 " \
        "{%0,%1,%2,%3}, {%4,%5,%6,%7}, {%8,%9}, {%0,%1,%2,%3};" \
        : "+f"((d)[0]), "+f"((d)[1]), "+f"((d)[2]), "+f"((d)[3]) \
        : "r"((a)[0]), "r"((a)[1]), "r"((a)[2]), "r"((a)[3]), "r"(b0_), "r"(b1_))

// ---------------------------------------------------------------------------
// One LC stage via warp-level bf16 split-precision MMA.
//  xin : [CI, HI, WI, B]   out : [CO, HO, WO, B]
// Block = one output position x 128 batch rows, 128 threads (4 warps).
// Warp w owns batch rows [w*32, w*32+32): 2 m16 tiles x (CO/8) n8 tiles.
// ---------------------------------------------------------------------------
template <int HO, int WO, int CO, int CI, int KK, int HI, int WI, int K>
__global__ void __launch_bounds__(128)
lc_mma(const float* __restrict__ xin, const unsigned char* __restrict__ wt,
       const float* __restrict__ bias, float* __restrict__ out, int B) {
    constexpr int KPAD = ((K + 31) / 32) * 32;
    constexpr int NCH = KPAD / 32;
    constexpr int CHB = CO * 68;
    constexpr int TILE = NCH * CHB;
    constexpr int NT = CO / 8;

    __shared__ __align__(16) uint32_t As_hi[128][17];
    __shared__ __align__(16) uint32_t As_lo[128][17];
    __shared__ __align__(16) uint32_t Bs_hi[CO][17];
    __shared__ __align__(16) uint32_t Bs_lo[CO][17];
    __shared__ int offs[KPAD];

    const int tid = threadIdx.x;
    const int w = tid >> 5;
    const int lane = tid & 31;
    const int g = lane >> 2;          // 0..7
    const int t = lane & 3;           // 0..3
    const int pos = blockIdx.x;
    const int i = pos / WO, j = pos % WO;
    const int b0 = blockIdx.y * 128;
    const int b = b0 + tid;

    // patch base offsets (batch-independent); k >= K -> offset 0 (weights are 0)
    for (int k = tid; k < KPAD; k += 128) {
        int v = 0;
        if (k < K) {
            int c = k / (KK * KK);
            int rem = k - c * KK * KK;
            int r = rem / KK, s = rem - r * KK;
            v = ((c * HI + i + r) * WI + (j + s)) * B;
        }
        offs[k] = v;
    }
    __syncthreads();

    float D[2][NT][4];
#pragma unroll
    for (int mt = 0; mt < 2; ++mt)
#pragma unroll
        for (int nt = 0; nt < NT; ++nt)
#pragma unroll
            for (int q = 0; q < 4; ++q) D[mt][nt][q] = 0.f;

    const unsigned char* wpos = wt + (size_t)pos * 2 * TILE;

    for (int c = 0; c < NCH; ++c) {
        if (c) __syncthreads();        // previous chunk's frag reads done
        // ---- A: gather 32 k-values for batch row 'tid', split hi/lo ----
        const int ck = c * 32;
#pragma unroll
        for (int q = 0; q < 16; ++q) {
            float v0 = __ldg(xin + offs[ck + 2 * q] + b);
            float v1 = __ldg(xin + offs[ck + 2 * q + 1] + b);
            __nv_bfloat16 h0 = __float2bfloat16(v0), h1 = __float2bfloat16(v1);
            __nv_bfloat16 l0 = __float2bfloat16(v0 - __bfloat162float(h0));
            __nv_bfloat16 l1 = __float2bfloat16(v1 - __bfloat162float(h1));
            As_hi[tid][q] = (uint32_t)__bfloat16_as_ushort(h0) |
                            ((uint32_t)__bfloat16_as_ushort(h1) << 16);
            As_lo[tid][q] = (uint32_t)__bfloat16_as_ushort(l0) |
                            ((uint32_t)__bfloat16_as_ushort(l1) << 16);
        }
        // ---- B: linear copy of pre-split chunk (hi + lo) ----
        {
            const uint4* sH = (const uint4*)(wpos + (size_t)c * CHB);
            const uint4* sL = (const uint4*)(wpos + TILE + (size_t)c * CHB);
            uint4* dH = (uint4*)&Bs_hi[0][0];
            uint4* dL = (uint4*)&Bs_lo[0][0];
            for (int idx = tid; idx < CHB / 16; idx += 128) {
                dH[idx] = sH[idx];
                dL[idx] = sL[idx];
            }
        }
        __syncthreads();

        // ---- compute: 2 k16 steps ----
#pragma unroll
        for (int ks = 0; ks < 2; ++ks) {
            const int base = ks * 8;
            uint32_t ah[2][4], al[2][4];
#pragma unroll
            for (int mt = 0; mt < 2; ++mt) {
                int m = w * 32 + mt * 16 + g;
                ah[mt][0] = As_hi[m][base + t];
                ah[mt][1] = As_hi[m + 8][base + t];
                ah[mt][2] = As_hi[m][base + t + 4];
                ah[mt][3] = As_hi[m + 8][base + t + 4];
                al[mt][0] = As_lo[m][base + t];
                al[mt][1] = As_lo[m + 8][base + t];
                al[mt][2] = As_lo[m][base + t + 4];
                al[mt][3] = As_lo[m + 8][base + t + 4];
            }
#pragma unroll
            for (int nt = 0; nt < NT; ++nt) {
                int n = nt * 8 + g;
                uint32_t bh0 = Bs_hi[n][base + t], bh1 = Bs_hi[n][base + t + 4];
                uint32_t bl0 = Bs_lo[n][base + t], bl1 = Bs_lo[n][base + t + 4];
#pragma unroll
                for (int mt = 0; mt < 2; ++mt) {
                    MMA_BF16(D[mt][nt], ah[mt], bh0, bh1);
                    MMA_BF16(D[mt][nt], ah[mt], bl0, bl1);
                    MMA_BF16(D[mt][nt], al[mt], bh0, bh1);
                }
            }
        }
    }

    // ---- epilogue: bias + tanh ----
#pragma unroll
    for (int mt = 0; mt < 2; ++mt) {
#pragma unroll
        for (int nt = 0; nt < NT; ++nt) {
            int n0 = nt * 8 + 2 * t;
            int m0 = b0 + w * 32 + mt * 16 + g;
            float bv0 = bias[pos * CO + n0];
            float bv1 = bias[pos * CO + n0 + 1];
            float* o00 = out + (size_t)((n0 * HO + i) * WO + j) * B + m0;
            float* o01 = out + (size_t)(((n0 + 1) * HO + i) * WO + j) * B + m0;
            o00[0] = tanhf(D[mt][nt][0] + bv0);
            o01[0] = tanhf(D[mt][nt][1] + bv1);
            o00[8] = tanhf(D[mt][nt][2] + bv0);
            o01[8] = tanhf(D[mt][nt][3] + bv1);
        }
    }
}

// ---------------------------------------------------------------------------
__global__ void head_kernel(const float* __restrict__ h, const float* __restrict__ info,
                            const float* __restrict__ hw, const float* __restrict__ hb,
                            float* __restrict__ out, int B) {
    __shared__ float w0[264], w1[264];
    for (int idx = threadIdx.x; idx < 264; idx += blockDim.x) {
        w0[idx] = hw[idx];
        w1[idx] = hw[264 + idx];
    }
    __syncthreads();
    int b = blockIdx.x * blockDim.x + threadIdx.x;
    if (b >= B) return;
    float l0 = hb[0], l1 = hb[1];
#pragma unroll 8
    for (int f = 0; f < 256; ++f) {
        float v = h[(size_t)f * B + b];
        l0 += v * w0[f];
        l1 += v * w1[f];
    }
#pragma unroll
    for (int q = 0; q < 8; ++q) {
        float v = info[(size_t)b * 8 + q];
        l0 += v * w0[256 + q];
        l1 += v * w1[256 + q];
    }
    float m = fmaxf(l0, l1);
    float e0 = expf(l0 - m), e1 = expf(l1 - m);
    float inv = 1.f / (e0 + e1);
    out[(size_t)b * 2 + 0] = e0 * inv;
    out[(size_t)b * 2 + 1] = e1 * inv;
}

// ---------------------------------------------------------------------------
// gmem weight byte offsets: 2 * NCH * CO * 68 per position
static const size_t W1OFF = 0;           // 256 * 8704   = 2,228,224
static const size_t W2OFF = 2228224;     // 144 * 28288  = 4,073,472
static const size_t W3OFF = 6301696;     // 100 * 21760  = 2,176,000
static const size_t W4OFF = 8477696;     // 64  * 39168  = 2,506,752
static const size_t W5OFF = 10984448;    // 36  * 39168  = 1,410,048
static const size_t W6OFF = 12394496;    // 16  * 78336  = 1,253,376
static const size_t W7OFF = 13647872;    // 4   * 156672 =   626,688

extern "C" void kernel_launch(void* const* d_in, const int* in_sizes, int n_in,
                              void* d_out, int out_size) {
    const float* x    = (const float*)d_in[0];
    const float* info = (const float*)d_in[1];
    const float* W1 = (const float*)d_in[2];  const float* b1 = (const float*)d_in[3];
    const float* W2 = (const float*)d_in[4];  const float* b2 = (const float*)d_in[5];
    const float* W3 = (const float*)d_in[6];  const float* b3 = (const float*)d_in[7];
    const float* W4 = (const float*)d_in[8];  const float* b4 = (const float*)d_in[9];
    const float* W5 = (const float*)d_in[10]; const float* b5 = (const float*)d_in[11];
    const float* W6 = (const float*)d_in[12]; const float* b6 = (const float*)d_in[13];
    const float* W7 = (const float*)d_in[14]; const float* b7 = (const float*)d_in[15];
    const float* hw = (const float*)d_in[16]; const float* hb = (const float*)d_in[17];
    float* out = (float*)d_out;

    const int B = in_sizes[0] / (5 * 20 * 20);

    float *xT, *bufA, *bufB;
    unsigned char* wt;
    cudaGetSymbolAddress((void**)&xT,   g_xT);
    cudaGetSymbolAddress((void**)&bufA, g_bufA);
    cudaGetSymbolAddress((void**)&bufB, g_bufB);
    cudaGetSymbolAddress((void**)&wt,   g_wt);

    // transpose input [B, 2000] -> [2000, B]
    {
        dim3 grid((2000 + 31) / 32, B / 32), block(32, 8);
        transpose2d<<<grid, block>>>(x, xT, B, 2000);
    }

    // weight prep (bf16 hi/lo, chunked layout)
    prep_w<16, 125><<<256, 256>>>(W1, wt + W1OFF);
    prep_w<16, 400><<<144, 256>>>(W2, wt + W2OFF);
    prep_w<32, 144><<<100, 256>>>(W3, wt + W3OFF);
    prep_w<32, 288><<<64,  256>>>(W4, wt + W4OFF);
    prep_w<32, 288><<<36,  256>>>(W5, wt + W5OFF);
    prep_w<64, 288><<<16,  256>>>(W6, wt + W6OFF);
    prep_w<64, 576><<<4,   256>>>(W7, wt + W7OFF);

    const int GY = B / 128;
    lc_mma<16,16,16, 5,5, 20,20, 125><<<dim3(256, GY), 128>>>(xT,   wt + W1OFF, b1, bufA, B);
    lc_mma<12,12,16, 16,5, 16,16, 400><<<dim3(144, GY), 128>>>(bufA, wt + W2OFF, b2, bufB, B);
    lc_mma<10,10,32, 16,3, 12,12, 144><<<dim3(100, GY), 128>>>(bufB, wt + W3OFF, b3, bufA, B);
    lc_mma<8,8,32,  32,3, 10,10, 288><<<dim3(64,  GY), 128>>>(bufA, wt + W4OFF, b4, bufB, B);
    lc_mma<6,6,32,  32,3, 8,8,   288><<<dim3(36,  GY), 128>>>(bufB, wt + W5OFF, b5, bufA, B);
    lc_mma<4,4,64,  32,3, 6,6,   288><<<dim3(16,  GY), 128>>>(bufA, wt + W6OFF, b6, bufB, B);
    lc_mma<2,2,64,  64,3, 4,4,   576><<<dim3(4,   GY), 128>>>(bufB, wt + W7OFF, b7, bufA, B);

    // head: bufA holds [64,2,2,B] == [256, B] in NCHW-flatten order
    head_kernel<<<(B + 255) / 256, 256>>>(bufA, info, hw, hb, out, B);
}

// round 10
// speedup vs baseline: 3.0017x; 2.2318x over previous
#include <cuda_runtime.h>
#include <cuda_bf16.h>
#include <cstdint>

#define BMAX 32768

// Activations stored packed: uint32 = bf16_hi | bf16_lo<<16, layout [feat][B]
__device__ uint32_t g_xT[5 * 20 * 20 * (size_t)BMAX];
__device__ uint32_t g_bufA[4096ull * BMAX];
__device__ uint32_t g_bufB[2304ull * BMAX];
__device__ __align__(16) uint32_t g_wt[3400000];   // fragment-major packed hi/lo weights

// ---------------------------------------------------------------------------
__device__ __forceinline__ uint32_t pack_hl(float v) {
    __nv_bfloat16 h = __float2bfloat16(v);
    float hf = __bfloat162float(h);
    __nv_bfloat16 l = __float2bfloat16(v - hf);
    return (uint32_t)__bfloat16_as_ushort(h) | ((uint32_t)__bfloat16_as_ushort(l) << 16);
}
__device__ __forceinline__ float unpack_hl(uint32_t w) {
    __nv_bfloat16 h = __ushort_as_bfloat16((unsigned short)(w & 0xFFFF));
    __nv_bfloat16 l = __ushort_as_bfloat16((unsigned short)(w >> 16));
    return __bfloat162float(h) + __bfloat162float(l);
}
__device__ __forceinline__ float ftanh(float x) {
    float xc = fminf(fmaxf(x, -9.f), 9.f);
    float e = __expf(2.f * xc);
    return __fdividef(e - 1.f, e + 1.f);
}

// ---------------------------------------------------------------------------
// transpose + split-pack: in[B, C] fp32 -> out[C, B] packed uint32
__global__ void transpose_pack(const float* __restrict__ in, uint32_t* __restrict__ out,
                               int R, int C) {
    __shared__ float t[32][33];
    int c = blockIdx.x * 32 + threadIdx.x;
    int r = blockIdx.y * 32 + threadIdx.y;
#pragma unroll
    for (int k = 0; k < 32; k += 8)
        if (c < C) t[threadIdx.y + k][threadIdx.x] = in[(size_t)(r + k) * C + c];
    __syncthreads();
    int co = blockIdx.y * 32 + threadIdx.x;
    int ro = blockIdx.x * 32 + threadIdx.y;
#pragma unroll
    for (int k = 0; k < 32; k += 8)
        if (ro + k < C) out[(size_t)(ro + k) * R + co] = pack_hl(t[threadIdx.x][threadIdx.y + k]);
}

// ---------------------------------------------------------------------------
// Weight prep: fragment-major packed layout.
// word index = ((c*2+ks)*NT + nt)*128 + lane*4 + q,  lane=(g,t)
//   q0: k=kb+2t, q1: k=kb+2t+1, q2: k=kb+2t+8, q3: k=kb+2t+9,  n = nt*8+g
// ---------------------------------------------------------------------------
template <int CO, int K>
__global__ void prep_w(const float* __restrict__ W, uint32_t* __restrict__ wf) {
    constexpr int KPAD = ((K + 31) / 32) * 32;
    constexpr int NCH = KPAD / 32;
    constexpr int NT = CO / 8;
    constexpr int WORDS = NCH * 2 * NT * 128;
    const int pos = blockIdx.x;
    uint32_t* dst = wf + (size_t)pos * WORDS;
    const float* src = W + (size_t)pos * CO * K;
    for (int idx = threadIdx.x; idx < WORDS; idx += blockDim.x) {
        int q = idx & 3;
        int lane = (idx >> 2) & 31;
        int rest = idx >> 7;
        int nt = rest % NT; rest /= NT;
        int ks = rest & 1;
        int c = rest >> 1;
        int g = lane >> 2, t = lane & 3;
        int k = c * 32 + ks * 16 + 2 * t + (q & 1) + 8 * (q >> 1);
        int n = nt * 8 + g;
        float v = (k < K) ? src[n * K + k] : 0.f;
        dst[idx] = pack_hl(v);
    }
}

// ---------------------------------------------------------------------------
#define MMA_BF16(d, a, b0_, b1_) \
    asm volatile("mma.sync.aligned.m16n8k16.row.col.f32.bf16.bf16.f32 " \
        "{%0,%1,%2,%3}, {%4,%5,%6,%7}, {%8,%9}, {%0,%1,%2,%3};" \
        : "+f"((d)[0]), "+f"((d)[1]), "+f"((d)[2]), "+f"((d)[3]) \
        : "r"((a)[0]), "r"((a)[1]), "r"((a)[2]), "r"((a)[3]), "r"(b0_), "r"(b1_))

// ---------------------------------------------------------------------------
// LC stage: direct-to-register fragment gather, no smem staging, no mainloop syncs.
// Block = one output position x 128 batch rows (4 warps x 32 rows).
// D += Ah*Bh + Ah*Bl + Al*Bh   (split bf16, fp32 accum)
// ---------------------------------------------------------------------------
template <int HO, int WO, int CO, int CI, int KK, int HI, int WI, int K>
__global__ void __launch_bounds__(128)
lc_frag(const uint32_t* __restrict__ xp, const uint32_t* __restrict__ wf,
        const float* __restrict__ bias, uint32_t* __restrict__ outp, int B) {
    constexpr int KPAD = ((K + 31) / 32) * 32;
    constexpr int NCH = KPAD / 32;
    constexpr int NT = CO / 8;

    __shared__ int offs[KPAD];

    const int tid = threadIdx.x;
    const int w = tid >> 5;
    const int lane = tid & 31;
    const int g = lane >> 2;
    const int t = lane & 3;
    const int pos = blockIdx.x;
    const int i = pos / WO, j = pos % WO;
    const int b0 = blockIdx.y * 128;

    for (int k = tid; k < KPAD; k += 128) {
        int v = 0;
        if (k < K) {
            int c = k / (KK * KK);
            int rem = k - c * KK * KK;
            int r = rem / KK, s = rem - r * KK;
            v = ((c * HI + i + r) * WI + (j + s)) * B;
        }
        offs[k] = v;
    }
    __syncthreads();

    float D[2][NT][4];
#pragma unroll
    for (int mt = 0; mt < 2; ++mt)
#pragma unroll
        for (int nt = 0; nt < NT; ++nt)
#pragma unroll
            for (int q = 0; q < 4; ++q) D[mt][nt][q] = 0.f;

    const uint32_t* wp = wf + (size_t)pos * (NCH * 2 * NT * 128);
    const int rbase = b0 + w * 32;

#pragma unroll 1
    for (int c = 0; c < NCH; ++c) {
#pragma unroll
        for (int ks = 0; ks < 2; ++ks) {
            const int kb = c * 32 + ks * 16 + 2 * t;
            const int o0 = offs[kb], o1 = offs[kb + 1];
            const int o2 = offs[kb + 8], o3 = offs[kb + 9];

            uint32_t ah[2][4], al[2][4];
#pragma unroll
            for (int mt = 0; mt < 2; ++mt) {
                const int ra = rbase + mt * 16 + g;
                const int rb = ra + 8;
                uint32_t x00 = __ldg(xp + o0 + ra), x10 = __ldg(xp + o1 + ra);
                uint32_t x01 = __ldg(xp + o0 + rb), x11 = __ldg(xp + o1 + rb);
                uint32_t x20 = __ldg(xp + o2 + ra), x30 = __ldg(xp + o3 + ra);
                uint32_t x21 = __ldg(xp + o2 + rb), x31 = __ldg(xp + o3 + rb);
                ah[mt][0] = __byte_perm(x00, x10, 0x5410); al[mt][0] = __byte_perm(x00, x10, 0x7632);
                ah[mt][1] = __byte_perm(x01, x11, 0x5410); al[mt][1] = __byte_perm(x01, x11, 0x7632);
                ah[mt][2] = __byte_perm(x20, x30, 0x5410); al[mt][2] = __byte_perm(x20, x30, 0x7632);
                ah[mt][3] = __byte_perm(x21, x31, 0x5410); al[mt][3] = __byte_perm(x21, x31, 0x7632);
            }

            const uint4* bptr = (const uint4*)(wp + (size_t)((c * 2 + ks) * NT) * 128) + lane;
#pragma unroll
            for (int nt = 0; nt < NT; ++nt) {
                uint4 bw = __ldg(bptr + nt * 32);
                uint32_t bh0 = __byte_perm(bw.x, bw.y, 0x5410);
                uint32_t bl0 = __byte_perm(bw.x, bw.y, 0x7632);
                uint32_t bh1 = __byte_perm(bw.z, bw.w, 0x5410);
                uint32_t bl1 = __byte_perm(bw.z, bw.w, 0x7632);
#pragma unroll
                for (int mt = 0; mt < 2; ++mt) {
                    MMA_BF16(D[mt][nt], ah[mt], bh0, bh1);
                    MMA_BF16(D[mt][nt], ah[mt], bl0, bl1);
                    MMA_BF16(D[mt][nt], al[mt], bh0, bh1);
                }
            }
        }
    }

    // epilogue: bias + tanh + split-pack store
#pragma unroll
    for (int mt = 0; mt < 2; ++mt) {
#pragma unroll
        for (int nt = 0; nt < NT; ++nt) {
            int n0 = nt * 8 + 2 * t;
            int m0 = b0 + w * 32 + mt * 16 + g;
            float bv0 = bias[pos * CO + n0];
            float bv1 = bias[pos * CO + n0 + 1];
            uint32_t* o0p = outp + (size_t)((n0 * HO + i) * WO + j) * B + m0;
            uint32_t* o1p = outp + (size_t)(((n0 + 1) * HO + i) * WO + j) * B + m0;
            o0p[0] = pack_hl(ftanh(D[mt][nt][0] + bv0));
            o1p[0] = pack_hl(ftanh(D[mt][nt][1] + bv1));
            o0p[8] = pack_hl(ftanh(D[mt][nt][2] + bv0));
            o1p[8] = pack_hl(ftanh(D[mt][nt][3] + bv1));
        }
    }
}

// ---------------------------------------------------------------------------
__global__ void head_kernel(const uint32_t* __restrict__ h, const float* __restrict__ info,
                            const float* __restrict__ hw, const float* __restrict__ hb,
                            float* __restrict__ out, int B) {
    __shared__ float w0[264], w1[264];
    for (int idx = threadIdx.x; idx < 264; idx += blockDim.x) {
        w0[idx] = hw[idx];
        w1[idx] = hw[264 + idx];
    }
    __syncthreads();
    int b = blockIdx.x * blockDim.x + threadIdx.x;
    if (b >= B) return;
    float l0 = hb[0], l1 = hb[1];
#pragma unroll 8
    for (int f = 0; f < 256; ++f) {
        float v = unpack_hl(h[(size_t)f * B + b]);
        l0 += v * w0[f];
        l1 += v * w1[f];
    }
#pragma unroll
    for (int q = 0; q < 8; ++q) {
        float v = info[(size_t)b * 8 + q];
        l0 += v * w0[256 + q];
        l1 += v * w1[256 + q];
    }
    float m = fmaxf(l0, l1);
    float e0 = expf(l0 - m), e1 = expf(l1 - m);
    float inv = 1.f / (e0 + e1);
    out[(size_t)b * 2 + 0] = e0 * inv;
    out[(size_t)b * 2 + 1] = e1 * inv;
}

// ---------------------------------------------------------------------------
// weight buffer offsets in uint32 words: NCH*2*NT*128 per position
static const size_t W1OFF = 0;         // 256 * 2048
static const size_t W2OFF = 524288;    // 144 * 6656
static const size_t W3OFF = 1482752;   // 100 * 5120
static const size_t W4OFF = 1994752;   // 64  * 9216
static const size_t W5OFF = 2584576;   // 36  * 9216
static const size_t W6OFF = 2916352;   // 16  * 18432
static const size_t W7OFF = 3211264;   // 4   * 36864  (end 3358720)

extern "C" void kernel_launch(void* const* d_in, const int* in_sizes, int n_in,
                              void* d_out, int out_size) {
    const float* x    = (const float*)d_in[0];
    const float* info = (const float*)d_in[1];
    const float* W1 = (const float*)d_in[2];  const float* b1 = (const float*)d_in[3];
    const float* W2 = (const float*)d_in[4];  const float* b2 = (const float*)d_in[5];
    const float* W3 = (const float*)d_in[6];  const float* b3 = (const float*)d_in[7];
    const float* W4 = (const float*)d_in[8];  const float* b4 = (const float*)d_in[9];
    const float* W5 = (const float*)d_in[10]; const float* b5 = (const float*)d_in[11];
    const float* W6 = (const float*)d_in[12]; const float* b6 = (const float*)d_in[13];
    const float* W7 = (const float*)d_in[14]; const float* b7 = (const float*)d_in[15];
    const float* hw = (const float*)d_in[16]; const float* hb = (const float*)d_in[17];
    float* out = (float*)d_out;

    const int B = in_sizes[0] / (5 * 20 * 20);

    uint32_t *xT, *bufA, *bufB, *wt;
    cudaGetSymbolAddress((void**)&xT,   g_xT);
    cudaGetSymbolAddress((void**)&bufA, g_bufA);
    cudaGetSymbolAddress((void**)&bufB, g_bufB);
    cudaGetSymbolAddress((void**)&wt,   g_wt);

    // transpose + split-pack input [B, 2000] -> [2000, B]
    {
        dim3 grid((2000 + 31) / 32, B / 32), block(32, 8);
        transpose_pack<<<grid, block>>>(x, xT, B, 2000);
    }

    // fragment-major packed weight prep
    prep_w<16, 125><<<256, 256>>>(W1, wt + W1OFF);
    prep_w<16, 400><<<144, 256>>>(W2, wt + W2OFF);
    prep_w<32, 144><<<100, 256>>>(W3, wt + W3OFF);
    prep_w<32, 288><<<64,  256>>>(W4, wt + W4OFF);
    prep_w<32, 288><<<36,  256>>>(W5, wt + W5OFF);
    prep_w<64, 288><<<16,  256>>>(W6, wt + W6OFF);
    prep_w<64, 576><<<4,   256>>>(W7, wt + W7OFF);

    const int GY = B / 128;
    lc_frag<16,16,16, 5,5, 20,20, 125><<<dim3(256, GY), 128>>>(xT,   wt + W1OFF, b1, bufA, B);
    lc_frag<12,12,16, 16,5, 16,16, 400><<<dim3(144, GY), 128>>>(bufA, wt + W2OFF, b2, bufB, B);
    lc_frag<10,10,32, 16,3, 12,12, 144><<<dim3(100, GY), 128>>>(bufB, wt + W3OFF, b3, bufA, B);
    lc_frag<8,8,32,  32,3, 10,10, 288><<<dim3(64,  GY), 128>>>(bufA, wt + W4OFF, b4, bufB, B);
    lc_frag<6,6,32,  32,3, 8,8,   288><<<dim3(36,  GY), 128>>>(bufB, wt + W5OFF, b5, bufA, B);
    lc_frag<4,4,64,  32,3, 6,6,   288><<<dim3(16,  GY), 128>>>(bufA, wt + W6OFF, b6, bufB, B);
    lc_frag<2,2,64,  64,3, 4,4,   576><<<dim3(4,   GY), 128>>>(bufB, wt + W7OFF, b7, bufA, B);

    // head: bufA holds [64,2,2,B] == [256, B] packed, NCHW-flatten order
    head_kernel<<<(B + 255) / 256, 256>>>(bufA, info, hw, hb, out, B);
}